// round 7
// baseline (speedup 1.0000x reference)
#include <cuda_runtime.h>
#include <math.h>

#define B1c 4
#define B2c 1024
#define Rc  64
#define Tc  8192
#define Lc  256
#define FULLM 0xFFFFFFFFu

// Lerp 4 outputs from a 5-value window starting at element E of this lane's
// float4 'a' (neighbor via shfl_down; lane31 patched from uniform 'bc'),
// accumulate into A (sum) and B (sum of squares).
template <int E>
static __device__ __forceinline__ void proc4(
    float4 a, float4 bc, bool last, float f,
    float& A0, float& A1, float& A2, float& A3,
    float& B0, float& B1, float& B2, float& B3)
{
    float v0, v1, v2, v3, v4;
    if (E == 0) {
        float nx = __shfl_down_sync(FULLM, a.x, 1);
        if (last) nx = bc.x;
        v0 = a.x; v1 = a.y; v2 = a.z; v3 = a.w; v4 = nx;
    } else if (E == 1) {
        float nx = __shfl_down_sync(FULLM, a.x, 1);
        float ny = __shfl_down_sync(FULLM, a.y, 1);
        if (last) { nx = bc.x; ny = bc.y; }
        v0 = a.y; v1 = a.z; v2 = a.w; v3 = nx; v4 = ny;
    } else if (E == 2) {
        float nx = __shfl_down_sync(FULLM, a.x, 1);
        float ny = __shfl_down_sync(FULLM, a.y, 1);
        float nz = __shfl_down_sync(FULLM, a.z, 1);
        if (last) { nx = bc.x; ny = bc.y; nz = bc.z; }
        v0 = a.z; v1 = a.w; v2 = nx; v3 = ny; v4 = nz;
    } else {
        float nx = __shfl_down_sync(FULLM, a.x, 1);
        float ny = __shfl_down_sync(FULLM, a.y, 1);
        float nz = __shfl_down_sync(FULLM, a.z, 1);
        float nw = __shfl_down_sync(FULLM, a.w, 1);
        if (last) { nx = bc.x; ny = bc.y; nz = bc.z; nw = bc.w; }
        v0 = a.w; v1 = nx; v2 = ny; v3 = nz; v4 = nw;
    }
    float o0 = fmaf(f, v1 - v0, v0);
    float o1 = fmaf(f, v2 - v1, v1);
    float o2 = fmaf(f, v3 - v2, v2);
    float o3 = fmaf(f, v4 - v3, v3);
    A0 += o0; A1 += o1; A2 += o2; A3 += o3;
    B0 = fmaf(o0, o0, B0);
    B1 = fmaf(o1, o1, B1);
    B2 = fmaf(o2, o2, B2);
    B3 = fmaf(o3, o3, B3);
}

__global__ __launch_bounds__(512, 4) void tof_kernel(
    const float* __restrict__ rec,    // (B1, R, T)
    const float* __restrict__ samp,   // (B1, B2, 3)
    const float* __restrict__ emit,   // (3,)
    const float* __restrict__ rcv,    // (R, 3)
    float* __restrict__ out)          // (B1, B2)
{
    __shared__ uint2 s_meta[Rc];      // {frac bits, (r*Tc + a0) | e<<24}
    __shared__ float s_A[8 * Lc];     // A_l partials per row-class, 8 KB
    __shared__ float s_red[32];

    const int tid  = threadIdx.x;
    const int warp = tid >> 5, lane = tid & 31;
    const int b2 = blockIdx.x, b1 = blockIdx.y;
    const float FSC = 96000.0f / 343.0f;

    // ---- Phase A: per-receiver start index, frac, alignment ----
    if (tid < Rc) {
        const int r = tid;
        const float* sp = samp + ((size_t)b1 * B2c + b2) * 3;
        float sx = sp[0], sy = sp[1], sz = sp[2];
        float ex = emit[0], ey = emit[1], ez = emit[2];
        float dx = sx - ex, dy = sy - ey, dz = sz - ez;
        float de = sqrtf(dx * dx + dy * dy + dz * dz);
        float rx = rcv[r * 3 + 0], ry = rcv[r * 3 + 1], rz = rcv[r * 3 + 2];
        dx = sx - rx; dy = sy - ry; dz = sz - rz;
        float dr = sqrtf(dx * dx + dy * dy + dz * dz);
        float start = (de + dr) * FSC;

        float fi = floorf(start);
        fi = fminf(fmaxf(fi, 0.0f), (float)(Tc - 2));
        int   i0   = (int)fi;
        float frac = start - fi;

        int a0 = i0 & ~3;
        a0 = min(a0, Tc - 264);              // memory-safety; inactive for real geometry
        int e = min(i0 - a0, 3);
        s_meta[r] = make_uint2(__float_as_uint(frac),
                               (unsigned)(r * Tc + a0) | ((unsigned)e << 24));
    }
    __syncthreads();

    // ---- Main loop ----
    // warp -> (row-class j = warp>>1, l-half h = warp&1)
    // iteration k: row r = 8k + j; lane covers l = 128h + 4lane .. +3
    const int h = warp & 1;
    const int j = warp >> 1;
    const int hoff = h << 7;
    const float* rec_b = rec + (size_t)b1 * (Rc * Tc);

    float A0 = 0.f, A1 = 0.f, A2 = 0.f, A3 = 0.f;
    float B0 = 0.f, B1 = 0.f, B2 = 0.f, B3 = 0.f;
    const bool last = (lane == 31);

#pragma unroll
    for (int k = 0; k < 8; k++) {
        int r = (k << 3) | j;
        uint2 m = s_meta[r];
        float f = __uint_as_float(m.x);
        const float* src = rec_b + (m.y & 0x00FFFFFFu) + hoff;
        int e = (int)(m.y >> 24);

        float4 a  = *(const float4*)(src + 4 * lane);   // elems hoff+4lane..+3
        float4 bc = *(const float4*)(src + 128);        // uniform: elems hoff+128..131

        if (e == 0)      proc4<0>(a, bc, last, f, A0, A1, A2, A3, B0, B1, B2, B3);
        else if (e == 1) proc4<1>(a, bc, last, f, A0, A1, A2, A3, B0, B1, B2, B3);
        else if (e == 2) proc4<2>(a, bc, last, f, A0, A1, A2, A3, B0, B1, B2, B3);
        else             proc4<3>(a, bc, last, f, A0, A1, A2, A3, B0, B1, B2, B3);
    }

    // ---- Epilogue ----
    // Per-row-class A_l partials: warp (j,h) owns l-range [hoff, hoff+128)
    *(float4*)&s_A[j * Lc + hoff + 4 * lane] = make_float4(A0, A1, A2, A3);

    // Per-thread nc partial: Sum over this thread's 4 l-slots of w_l^2 * B
    const float PI255 = (float)(3.14159265358979323846 / 255.0);
    const int l0 = hoff + 4 * lane;
    float ncp;
    {
        float w0 = 0.5f - 0.5f * __cosf(PI255 * (float)(l0 + 0));
        float w1 = 0.5f - 0.5f * __cosf(PI255 * (float)(l0 + 1));
        float w2 = 0.5f - 0.5f * __cosf(PI255 * (float)(l0 + 2));
        float w3 = 0.5f - 0.5f * __cosf(PI255 * (float)(l0 + 3));
        ncp = w0 * w0 * B0;
        ncp = fmaf(w1 * w1, B1, ncp);
        ncp = fmaf(w2 * w2, B2, ncp);
        ncp = fmaf(w3 * w3, B3, ncp);
    }
    __syncthreads();

    // Threads 0..255: slot l = tid; full-R A sum, then w^2 * A^2
    float dcp = 0.f;
    if (tid < Lc) {
        float Asum = 0.f;
#pragma unroll
        for (int jj = 0; jj < 8; jj++) Asum += s_A[jj * Lc + tid];
        float wl = 0.5f - 0.5f * __cosf(PI255 * (float)tid);
        dcp = (wl * wl) * Asum * Asum;
    }

    // Block reduction of (ncp, dcp)
#pragma unroll
    for (int o = 16; o > 0; o >>= 1) {
        ncp += __shfl_down_sync(FULLM, ncp, o);
        dcp += __shfl_down_sync(FULLM, dcp, o);
    }
    if (lane == 0) { s_red[warp] = ncp; s_red[16 + warp] = dcp; }
    __syncthreads();
    if (tid == 0) {
        float n = 0.f, d = 0.f;
#pragma unroll
        for (int w16 = 0; w16 < 16; w16++) { n += s_red[w16]; d += s_red[16 + w16]; }
        // num = n/(R*L);  den = (n - d/R)/((R-1)*L) + 0.001
        float num = n * (1.0f / (Rc * Lc));
        float den = (n - d * (1.0f / Rc)) * (1.0f / ((Rc - 1) * Lc)) + 0.001f;
        out[(size_t)b1 * B2c + b2] = num / den;
    }
}

extern "C" void kernel_launch(void* const* d_in, const int* in_sizes, int n_in,
                              void* d_out, int out_size)
{
    const float* rec  = (const float*)d_in[0];
    const float* samp = (const float*)d_in[1];
    const float* emit = (const float*)d_in[2];
    const float* rcv  = (const float*)d_in[3];
    float* out = (float*)d_out;

    dim3 grid(B2c, B1c);
    tof_kernel<<<grid, 512>>>(rec, samp, emit, rcv, out);
}